// round 2
// baseline (speedup 1.0000x reference)
#include <cuda_runtime.h>
#include <cuda_fp16.h>
#include <stdint.h>

// RNN1DGeneral: B=16384, L=64, H=64, DEPTH=2, D_L=2, D_C=8, LPF=0.5
// fp16 mma.sync.m16n8k16; hidden state lives in registers as A-fragments
// across all 65 steps. 128 CTAs x 128 threads; each warp owns 32 batch rows.

__device__ __forceinline__ void mma16816(float* c,
    uint32_t a0, uint32_t a1, uint32_t a2, uint32_t a3,
    uint32_t b0, uint32_t b1)
{
    asm("mma.sync.aligned.m16n8k16.row.col.f32.f16.f16.f32 "
        "{%0,%1,%2,%3},{%4,%5,%6,%7},{%8,%9},{%0,%1,%2,%3};"
        : "+f"(c[0]), "+f"(c[1]), "+f"(c[2]), "+f"(c[3])
        : "r"(a0), "r"(a1), "r"(a2), "r"(a3), "r"(b0), "r"(b1));
}

__device__ __forceinline__ uint32_t pack2(float lo, float hi) {
    __half2 h = __floats2half2_rn(lo, hi);
    return *reinterpret_cast<const uint32_t*>(&h);
}

__global__ void __launch_bounds__(128, 1) rnn_fused(
    const int*   __restrict__ x,     // [16384, 65]
    const float* __restrict__ Win0,  // [2, 64]
    const float* __restrict__ Win1,  // [64, 64]
    const float* __restrict__ Wh,    // [2, 64, 64]
    const float* __restrict__ bvec,  // [2, 64]
    const float* __restrict__ Wlat,  // [64, 2]
    const float* __restrict__ blat,  // [2]
    const float* __restrict__ Wcav,  // [128, 8]
    const float* __restrict__ bcav,  // [8]
    float*       __restrict__ out)   // [16384]
{
    // n-major fp16 weights, stride 72 halves (conflict-free B-fragment LDS)
    __shared__ __half sW[3][64][72];   // 0: Wh0, 1: Win1, 2: Wh1  (sW[l][n][k])
    __shared__ __half sAug[2][64][24]; // aug0: k0,k1=Win0 rows, k2=b0; aug1: k0=b1
    __shared__ float  sWlat[64][2];
    __shared__ float  sCav[128][8];
    __shared__ float  sB[10];          // [0..7]=bcav, [8..9]=blat

    const int tid = threadIdx.x;

    for (int i = tid; i < 64 * 64; i += 128) {
        int k = i >> 6, n = i & 63;
        sW[0][n][k] = __float2half(Wh[k * 64 + n]);
        sW[1][n][k] = __float2half(Win1[k * 64 + n]);
        sW[2][n][k] = __float2half(Wh[4096 + k * 64 + n]);
    }
    for (int i = tid; i < 2 * 64 * 24; i += 128)
        (reinterpret_cast<__half*>(sAug))[i] = __ushort_as_half((unsigned short)0);
    for (int i = tid; i < 128 * 8; i += 128)
        (reinterpret_cast<float*>(sCav))[i] = Wcav[i];
    if (tid < 8) sB[tid] = bcav[tid];
    if (tid < 2) sB[8 + tid] = blat[tid];
    __syncthreads();
    if (tid < 64) {
        int n = tid;
        sAug[0][n][0] = __float2half(Win0[n]);
        sAug[0][n][1] = __float2half(Win0[64 + n]);
        sAug[0][n][2] = __float2half(bvec[n]);
        sAug[1][n][0] = __float2half(bvec[64 + n]);
        sWlat[n][0] = Wlat[2 * n];
        sWlat[n][1] = Wlat[2 * n + 1];
    }
    __syncthreads();

    const int lane = tid & 31, warp = tid >> 5;
    const int q = lane >> 2, m = lane & 3;
    const int rowbase = blockIdx.x * 128 + warp * 32;

    // pack per-row input bits; rr = mt*2 + h  ->  row = rowbase+16*mt+q+8*h
    uint64_t xb[4];
    int xl[4];
#pragma unroll
    for (int rr = 0; rr < 4; rr++) {
        int r = rowbase + (rr >> 1) * 16 + q + (rr & 1) * 8;
        const int* xr = x + r * 65;
        uint64_t bits = 0;
#pragma unroll 8
        for (int t = 0; t < 64; t++)
            bits |= ((uint64_t)(xr[t] & 1)) << t;
        xb[rr] = bits;
        xl[rr] = xr[64] & 7;
    }

    // per-lane Wlat columns (this thread's cols: 8*nt + 2*m + j)
    float wl[8][2][2];
#pragma unroll
    for (int nt = 0; nt < 8; nt++)
#pragma unroll
        for (int j = 0; j < 2; j++) {
            int col = 8 * nt + 2 * m + j;
            wl[nt][j][0] = sWlat[col][0];
            wl[nt][j][1] = sWlat[col][1];
        }
    const float bl0 = sB[8], bl1 = sB[9];

    // hidden state A-fragments, zero init
    uint32_t h0f[2][4][4], h1f[2][4][4];
#pragma unroll
    for (int mt = 0; mt < 2; mt++)
#pragma unroll
        for (int kt = 0; kt < 4; kt++)
#pragma unroll
            for (int i = 0; i < 4; i++) { h0f[mt][kt][i] = 0u; h1f[mt][kt][i] = 0u; }

    float lp[4] = {0.f, 0.f, 0.f, 0.f};
    float acc[2][8][4];

#pragma unroll 1
    for (int step = 0; step < 65; step++) {
#pragma unroll
        for (int mt = 0; mt < 2; mt++)
#pragma unroll
            for (int nt = 0; nt < 8; nt++)
#pragma unroll
                for (int i = 0; i < 4; i++) acc[mt][nt][i] = 0.f;

        // ---- layer 0: elu(h0 @ Wh0 + onehot(prev) @ Win0 + b0) ----
#pragma unroll
        for (int kt = 0; kt < 4; kt++)
#pragma unroll
            for (int nt = 0; nt < 8; nt++) {
                const uint32_t* bp =
                    reinterpret_cast<const uint32_t*>(&sW[0][8 * nt + q][16 * kt + 2 * m]);
                uint32_t b0 = bp[0], b1 = bp[4];
                mma16816(acc[0][nt], h0f[0][kt][0], h0f[0][kt][1], h0f[0][kt][2], h0f[0][kt][3], b0, b1);
                mma16816(acc[1][nt], h1f[0][0][0] * 0u + h0f[1][kt][0], h0f[1][kt][1], h0f[1][kt][2], h0f[1][kt][3], b0, b1);
            }
        // augmented input tile: one-hot(prev) at k=0/1, 1.0 at k=2 (bias)
        uint32_t aa[2][2];
#pragma unroll
        for (int mt = 0; mt < 2; mt++)
#pragma unroll
            for (int h = 0; h < 2; h++) {
                uint32_t v = 0u;
                if (m == 0) {
                    if (step > 0) {
                        int bit = (int)((xb[mt * 2 + h] >> (step - 1)) & 1ull);
                        v = bit ? 0x3C000000u : 0x00003C00u;
                    }
                } else if (m == 1) {
                    v = 0x00003C00u;  // col 2 = bias row
                }
                aa[mt][h] = v;
            }
#pragma unroll
        for (int nt = 0; nt < 8; nt++) {
            const uint32_t* bp =
                reinterpret_cast<const uint32_t*>(&sAug[0][8 * nt + q][2 * m]);
            uint32_t b0 = bp[0], b1 = bp[4];
            mma16816(acc[0][nt], aa[0][0], aa[0][1], 0u, 0u, b0, b1);
            mma16816(acc[1][nt], aa[1][0], aa[1][1], 0u, 0u, b0, b1);
        }
#pragma unroll
        for (int mt = 0; mt < 2; mt++)
#pragma unroll
            for (int nt = 0; nt < 8; nt++)
#pragma unroll
                for (int i = 0; i < 4; i++) {
                    float v = acc[mt][nt][i];
                    acc[mt][nt][i] = v > 0.f ? v : (__expf(v) - 1.f);
                }
        // C-fragment -> A-fragment repack (register-only)
#pragma unroll
        for (int mt = 0; mt < 2; mt++)
#pragma unroll
            for (int kt = 0; kt < 4; kt++) {
                h0f[mt][kt][0] = pack2(acc[mt][2 * kt][0], acc[mt][2 * kt][1]);
                h0f[mt][kt][1] = pack2(acc[mt][2 * kt][2], acc[mt][2 * kt][3]);
                h0f[mt][kt][2] = pack2(acc[mt][2 * kt + 1][0], acc[mt][2 * kt + 1][1]);
                h0f[mt][kt][3] = pack2(acc[mt][2 * kt + 1][2], acc[mt][2 * kt + 1][3]);
            }

        // ---- layer 1: elu(h1 @ Wh1 + h0_new @ Win1 + b1) ----
#pragma unroll
        for (int mt = 0; mt < 2; mt++)
#pragma unroll
            for (int nt = 0; nt < 8; nt++)
#pragma unroll
                for (int i = 0; i < 4; i++) acc[mt][nt][i] = 0.f;
#pragma unroll
        for (int kt = 0; kt < 4; kt++)
#pragma unroll
            for (int nt = 0; nt < 8; nt++) {
                const uint32_t* bp =
                    reinterpret_cast<const uint32_t*>(&sW[2][8 * nt + q][16 * kt + 2 * m]);
                uint32_t b0 = bp[0], b1 = bp[4];
                mma16816(acc[0][nt], h1f[0][kt][0], h1f[0][kt][1], h1f[0][kt][2], h1f[0][kt][3], b0, b1);
                mma16816(acc[1][nt], h1f[1][kt][0], h1f[1][kt][1], h1f[1][kt][2], h1f[1][kt][3], b0, b1);
            }
#pragma unroll
        for (int kt = 0; kt < 4; kt++)
#pragma unroll
            for (int nt = 0; nt < 8; nt++) {
                const uint32_t* bp =
                    reinterpret_cast<const uint32_t*>(&sW[1][8 * nt + q][16 * kt + 2 * m]);
                uint32_t b0 = bp[0], b1 = bp[4];
                mma16816(acc[0][nt], h0f[0][kt][0], h0f[0][kt][1], h0f[0][kt][2], h0f[0][kt][3], b0, b1);
                mma16816(acc[1][nt], h0f[1][kt][0], h0f[1][kt][1], h0f[1][kt][2], h0f[1][kt][3], b0, b1);
            }
        {
            uint32_t ab = (m == 0) ? 0x00003C00u : 0u;  // bias row at k=0
#pragma unroll
            for (int nt = 0; nt < 8; nt++) {
                const uint32_t* bp =
                    reinterpret_cast<const uint32_t*>(&sAug[1][8 * nt + q][2 * m]);
                uint32_t b0 = bp[0], b1 = bp[4];
                mma16816(acc[0][nt], ab, ab, 0u, 0u, b0, b1);
                mma16816(acc[1][nt], ab, ab, 0u, 0u, b0, b1);
            }
        }
#pragma unroll
        for (int mt = 0; mt < 2; mt++)
#pragma unroll
            for (int nt = 0; nt < 8; nt++)
#pragma unroll
                for (int i = 0; i < 4; i++) {
                    float v = acc[mt][nt][i];
                    acc[mt][nt][i] = v > 0.f ? v : (__expf(v) - 1.f);
                }
#pragma unroll
        for (int mt = 0; mt < 2; mt++)
#pragma unroll
            for (int kt = 0; kt < 4; kt++) {
                h1f[mt][kt][0] = pack2(acc[mt][2 * kt][0], acc[mt][2 * kt][1]);
                h1f[mt][kt][1] = pack2(acc[mt][2 * kt][2], acc[mt][2 * kt][3]);
                h1f[mt][kt][2] = pack2(acc[mt][2 * kt + 1][0], acc[mt][2 * kt + 1][1]);
                h1f[mt][kt][3] = pack2(acc[mt][2 * kt + 1][2], acc[mt][2 * kt + 1][3]);
            }

        // ---- per-step logits head (steps 0..63) ----
        if (step < 64) {
#pragma unroll
            for (int mt = 0; mt < 2; mt++)
#pragma unroll
                for (int h = 0; h < 2; h++) {
                    float z0 = 0.f, z1 = 0.f;
#pragma unroll
                    for (int nt = 0; nt < 8; nt++) {
                        float c0 = acc[mt][nt][2 * h];
                        float c1 = acc[mt][nt][2 * h + 1];
                        z0 += c0 * wl[nt][0][0] + c1 * wl[nt][1][0];
                        z1 += c0 * wl[nt][0][1] + c1 * wl[nt][1][1];
                    }
                    z0 += __shfl_xor_sync(0xffffffffu, z0, 1);
                    z0 += __shfl_xor_sync(0xffffffffu, z0, 2);
                    z1 += __shfl_xor_sync(0xffffffffu, z1, 1);
                    z1 += __shfl_xor_sync(0xffffffffu, z1, 2);
                    z0 += bl0; z1 += bl1;
                    int rr = mt * 2 + h;
                    int bit = (int)((xb[rr] >> step) & 1ull);
                    float mx = fmaxf(z0, z1);
                    float lse = mx + __logf(1.f + __expf(-fabsf(z0 - z1)));
                    float zsel = bit ? z1 : z0;
                    lp[rr] += 0.5f * (zsel - lse);
                }
        }
    }

    // ---- cavity head: hF=[h0_final, h1_final] (128) @ Wcav + bcav ----
#pragma unroll
    for (int rr = 0; rr < 4; rr++) {
        int mt = rr >> 1, h = rr & 1;
        float zc[8];
#pragma unroll
        for (int c = 0; c < 8; c++) zc[c] = 0.f;
#pragma unroll
        for (int nt = 0; nt < 8; nt++) {
            int kt = nt >> 1;
            int ri = 2 * (nt & 1) + h;
            __half2 h2 = *reinterpret_cast<const __half2*>(&h0f[mt][kt][ri]);
            float v0 = __half2float(__low2half(h2));
            float v1 = __half2float(__high2half(h2));
            float a0v = acc[mt][nt][2 * h];
            float a1v = acc[mt][nt][2 * h + 1];
            int col = 8 * nt + 2 * m;
#pragma unroll
            for (int c = 0; c < 8; c++) {
                zc[c] += v0 * sCav[col][c] + v1 * sCav[col + 1][c]
                       + a0v * sCav[64 + col][c] + a1v * sCav[64 + col + 1][c];
            }
        }
#pragma unroll
        for (int c = 0; c < 8; c++) {
            zc[c] += __shfl_xor_sync(0xffffffffu, zc[c], 1);
            zc[c] += __shfl_xor_sync(0xffffffffu, zc[c], 2);
            zc[c] += sB[c];
        }
        float mx = zc[0];
#pragma unroll
        for (int c = 1; c < 8; c++) mx = fmaxf(mx, zc[c]);
        float s = 0.f;
#pragma unroll
        for (int c = 0; c < 8; c++) s += __expf(zc[c] - mx);
        float lse = mx + __logf(s);
        float zsel = zc[0];
#pragma unroll
        for (int c = 1; c < 8; c++) if (xl[rr] == c) zsel = zc[c];
        float total = lp[rr] + 0.5f * (zsel - lse);
        if (m == 0) {
            int row = rowbase + 16 * mt + q + 8 * h;
            out[row] = total;
        }
    }
}

extern "C" void kernel_launch(void* const* d_in, const int* in_sizes, int n_in,
                              void* d_out, int out_size) {
    (void)in_sizes; (void)n_in; (void)out_size;
    const int*   x    = (const int*)d_in[0];
    const float* Win0 = (const float*)d_in[1];
    const float* Win1 = (const float*)d_in[2];
    const float* Wh   = (const float*)d_in[3];
    const float* b    = (const float*)d_in[4];
    const float* Wlat = (const float*)d_in[5];
    const float* blat = (const float*)d_in[6];
    const float* Wcav = (const float*)d_in[7];
    const float* bcav = (const float*)d_in[8];
    float* out = (float*)d_out;
    rnn_fused<<<128, 128>>>(x, Win0, Win1, Wh, b, Wlat, blat, Wcav, bcav, out);
}

// round 3
// speedup vs baseline: 1.6026x; 1.6026x over previous
#include <cuda_runtime.h>
#include <cuda_fp16.h>
#include <stdint.h>

// RNN1DGeneral: B=16384, L=64, H=64, DEPTH=2, D_L=2, D_C=8, LPF=0.5
// fp16 mma.sync.m16n8k16; hidden state in registers across all 65 steps.
// R3: 256 threads/CTA (8 warps), 16 rows/warp (1 m-tile), grid=128.
// 2 warps/SMSP so MMA phases of one warp hide scalar phases of the other.

__device__ __forceinline__ void mma16816(float* c,
    uint32_t a0, uint32_t a1, uint32_t a2, uint32_t a3,
    uint32_t b0, uint32_t b1)
{
    asm("mma.sync.aligned.m16n8k16.row.col.f32.f16.f16.f32 "
        "{%0,%1,%2,%3},{%4,%5,%6,%7},{%8,%9},{%0,%1,%2,%3};"
        : "+f"(c[0]), "+f"(c[1]), "+f"(c[2]), "+f"(c[3])
        : "r"(a0), "r"(a1), "r"(a2), "r"(a3), "r"(b0), "r"(b1));
}

__device__ __forceinline__ uint32_t pack2(float lo, float hi) {
    __half2 h = __floats2half2_rn(lo, hi);
    return *reinterpret_cast<const uint32_t*>(&h);
}

__global__ void __launch_bounds__(256, 1) rnn_fused(
    const int*   __restrict__ x,     // [16384, 65]
    const float* __restrict__ Win0,  // [2, 64]
    const float* __restrict__ Win1,  // [64, 64]
    const float* __restrict__ Wh,    // [2, 64, 64]
    const float* __restrict__ bvec,  // [2, 64]
    const float* __restrict__ Wlat,  // [64, 2]
    const float* __restrict__ blat,  // [2]
    const float* __restrict__ Wcav,  // [128, 8]
    const float* __restrict__ bcav,  // [8]
    float*       __restrict__ out)   // [16384]
{
    // n-major fp16 weights, stride 72 halves (conflict-free B-fragment LDS)
    __shared__ __half sW[3][64][72];   // 0: Wh0, 1: Win1, 2: Wh1  (sW[l][n][k])
    __shared__ __half sAug[2][64][24]; // aug0: k0,k1=Win0 rows, k2=b0; aug1: k0=b1
    __shared__ float  sWlat[64][2];
    __shared__ float  sCav[128][8];
    __shared__ float  sB[10];          // [0..7]=bcav, [8..9]=blat

    const int tid = threadIdx.x;

    for (int i = tid; i < 64 * 64; i += 256) {
        int k = i >> 6, n = i & 63;
        sW[0][n][k] = __float2half(Wh[k * 64 + n]);
        sW[1][n][k] = __float2half(Win1[k * 64 + n]);
        sW[2][n][k] = __float2half(Wh[4096 + k * 64 + n]);
    }
    for (int i = tid; i < 2 * 64 * 24; i += 256)
        (reinterpret_cast<__half*>(sAug))[i] = __ushort_as_half((unsigned short)0);
    for (int i = tid; i < 128 * 8; i += 256)
        (reinterpret_cast<float*>(sCav))[i] = Wcav[i];
    if (tid < 8) sB[tid] = bcav[tid];
    if (tid < 2) sB[8 + tid] = blat[tid];
    __syncthreads();
    if (tid < 64) {
        int n = tid;
        sAug[0][n][0] = __float2half(Win0[n]);
        sAug[0][n][1] = __float2half(Win0[64 + n]);
        sAug[0][n][2] = __float2half(bvec[n]);
        sAug[1][n][0] = __float2half(bvec[64 + n]);
        sWlat[n][0] = Wlat[2 * n];
        sWlat[n][1] = Wlat[2 * n + 1];
    }
    __syncthreads();

    const int lane = tid & 31, warp = tid >> 5;
    const int q = lane >> 2, m = lane & 3;
    const int rowbase = blockIdx.x * 128 + warp * 16;

    // pack per-row input bits; rr = h in {0,1} -> row = rowbase + q + 8*h
    uint64_t xb[2];
    int xl[2];
#pragma unroll
    for (int rr = 0; rr < 2; rr++) {
        int r = rowbase + q + rr * 8;
        const int* xr = x + r * 65;
        uint64_t bits = 0;
#pragma unroll 8
        for (int t = 0; t < 64; t++)
            bits |= ((uint64_t)(xr[t] & 1)) << t;
        xb[rr] = bits;
        xl[rr] = xr[64] & 7;
    }

    // per-lane Wlat columns (this thread's cols: 8*nt + 2*m + j)
    float wl[8][2][2];
#pragma unroll
    for (int nt = 0; nt < 8; nt++)
#pragma unroll
        for (int j = 0; j < 2; j++) {
            int col = 8 * nt + 2 * m + j;
            wl[nt][j][0] = sWlat[col][0];
            wl[nt][j][1] = sWlat[col][1];
        }
    const float bl0 = sB[8], bl1 = sB[9];

    // hidden state A-fragments, zero init
    uint32_t h0f[4][4], h1f[4][4];
#pragma unroll
    for (int kt = 0; kt < 4; kt++)
#pragma unroll
        for (int i = 0; i < 4; i++) { h0f[kt][i] = 0u; h1f[kt][i] = 0u; }

    float lp[2] = {0.f, 0.f};
    float acc[8][4];

#pragma unroll 1
    for (int step = 0; step < 65; step++) {
#pragma unroll
        for (int nt = 0; nt < 8; nt++)
#pragma unroll
            for (int i = 0; i < 4; i++) acc[nt][i] = 0.f;

        // ---- layer 0: elu(h0 @ Wh0 + onehot(prev) @ Win0 + b0) ----
#pragma unroll
        for (int kt = 0; kt < 4; kt++)
#pragma unroll
            for (int nt = 0; nt < 8; nt++) {
                const uint32_t* bp =
                    reinterpret_cast<const uint32_t*>(&sW[0][8 * nt + q][16 * kt + 2 * m]);
                mma16816(acc[nt], h0f[kt][0], h0f[kt][1], h0f[kt][2], h0f[kt][3],
                         bp[0], bp[4]);
            }
        // augmented input tile: one-hot(prev) at k=0/1, 1.0 at k=2 (bias)
        uint32_t aa[2];
#pragma unroll
        for (int h = 0; h < 2; h++) {
            uint32_t v = 0u;
            if (m == 0) {
                if (step > 0) {
                    int bit = (int)((xb[h] >> (step - 1)) & 1ull);
                    v = bit ? 0x3C000000u : 0x00003C00u;
                }
            } else if (m == 1) {
                v = 0x00003C00u;  // col 2 = bias row
            }
            aa[h] = v;
        }
#pragma unroll
        for (int nt = 0; nt < 8; nt++) {
            const uint32_t* bp =
                reinterpret_cast<const uint32_t*>(&sAug[0][8 * nt + q][2 * m]);
            mma16816(acc[nt], aa[0], aa[1], 0u, 0u, bp[0], bp[4]);
        }
#pragma unroll
        for (int nt = 0; nt < 8; nt++)
#pragma unroll
            for (int i = 0; i < 4; i++) {
                float v = acc[nt][i];
                acc[nt][i] = v > 0.f ? v : (__expf(v) - 1.f);
            }
        // C-fragment -> A-fragment repack (register-only)
#pragma unroll
        for (int kt = 0; kt < 4; kt++) {
            h0f[kt][0] = pack2(acc[2 * kt][0], acc[2 * kt][1]);
            h0f[kt][1] = pack2(acc[2 * kt][2], acc[2 * kt][3]);
            h0f[kt][2] = pack2(acc[2 * kt + 1][0], acc[2 * kt + 1][1]);
            h0f[kt][3] = pack2(acc[2 * kt + 1][2], acc[2 * kt + 1][3]);
        }

        // ---- layer 1: elu(h1 @ Wh1 + h0_new @ Win1 + b1) ----
#pragma unroll
        for (int nt = 0; nt < 8; nt++)
#pragma unroll
            for (int i = 0; i < 4; i++) acc[nt][i] = 0.f;
#pragma unroll
        for (int kt = 0; kt < 4; kt++)
#pragma unroll
            for (int nt = 0; nt < 8; nt++) {
                const uint32_t* bp =
                    reinterpret_cast<const uint32_t*>(&sW[2][8 * nt + q][16 * kt + 2 * m]);
                mma16816(acc[nt], h1f[kt][0], h1f[kt][1], h1f[kt][2], h1f[kt][3],
                         bp[0], bp[4]);
            }
#pragma unroll
        for (int kt = 0; kt < 4; kt++)
#pragma unroll
            for (int nt = 0; nt < 8; nt++) {
                const uint32_t* bp =
                    reinterpret_cast<const uint32_t*>(&sW[1][8 * nt + q][16 * kt + 2 * m]);
                mma16816(acc[nt], h0f[kt][0], h0f[kt][1], h0f[kt][2], h0f[kt][3],
                         bp[0], bp[4]);
            }
        {
            uint32_t ab = (m == 0) ? 0x00003C00u : 0u;  // bias row at k=0
#pragma unroll
            for (int nt = 0; nt < 8; nt++) {
                const uint32_t* bp =
                    reinterpret_cast<const uint32_t*>(&sAug[1][8 * nt + q][2 * m]);
                mma16816(acc[nt], ab, ab, 0u, 0u, bp[0], bp[4]);
            }
        }
#pragma unroll
        for (int nt = 0; nt < 8; nt++)
#pragma unroll
            for (int i = 0; i < 4; i++) {
                float v = acc[nt][i];
                acc[nt][i] = v > 0.f ? v : (__expf(v) - 1.f);
            }
#pragma unroll
        for (int kt = 0; kt < 4; kt++) {
            h1f[kt][0] = pack2(acc[2 * kt][0], acc[2 * kt][1]);
            h1f[kt][1] = pack2(acc[2 * kt][2], acc[2 * kt][3]);
            h1f[kt][2] = pack2(acc[2 * kt + 1][0], acc[2 * kt + 1][1]);
            h1f[kt][3] = pack2(acc[2 * kt + 1][2], acc[2 * kt + 1][3]);
        }

        // ---- per-step logits head (steps 0..63) ----
        if (step < 64) {
#pragma unroll
            for (int h = 0; h < 2; h++) {
                float z0 = 0.f, z1 = 0.f;
#pragma unroll
                for (int nt = 0; nt < 8; nt++) {
                    float c0 = acc[nt][2 * h];
                    float c1 = acc[nt][2 * h + 1];
                    z0 += c0 * wl[nt][0][0] + c1 * wl[nt][1][0];
                    z1 += c0 * wl[nt][0][1] + c1 * wl[nt][1][1];
                }
                z0 += __shfl_xor_sync(0xffffffffu, z0, 1);
                z0 += __shfl_xor_sync(0xffffffffu, z0, 2);
                z1 += __shfl_xor_sync(0xffffffffu, z1, 1);
                z1 += __shfl_xor_sync(0xffffffffu, z1, 2);
                z0 += bl0; z1 += bl1;
                int bit = (int)((xb[h] >> step) & 1ull);
                float mx = fmaxf(z0, z1);
                float lse = mx + __logf(1.f + __expf(-fabsf(z0 - z1)));
                float zsel = bit ? z1 : z0;
                lp[h] += 0.5f * (zsel - lse);
            }
        }
    }

    // ---- cavity head: hF=[h0_final, h1_final] (128) @ Wcav + bcav ----
#pragma unroll
    for (int h = 0; h < 2; h++) {
        float zc[8];
#pragma unroll
        for (int c = 0; c < 8; c++) zc[c] = 0.f;
#pragma unroll
        for (int nt = 0; nt < 8; nt++) {
            int kt = nt >> 1;
            int ri = 2 * (nt & 1) + h;
            __half2 h2 = *reinterpret_cast<const __half2*>(&h0f[kt][ri]);
            float v0 = __half2float(__low2half(h2));
            float v1 = __half2float(__high2half(h2));
            float a0v = acc[nt][2 * h];
            float a1v = acc[nt][2 * h + 1];
            int col = 8 * nt + 2 * m;
#pragma unroll
            for (int c = 0; c < 8; c++) {
                zc[c] += v0 * sCav[col][c] + v1 * sCav[col + 1][c]
                       + a0v * sCav[64 + col][c] + a1v * sCav[64 + col + 1][c];
            }
        }
#pragma unroll
        for (int c = 0; c < 8; c++) {
            zc[c] += __shfl_xor_sync(0xffffffffu, zc[c], 1);
            zc[c] += __shfl_xor_sync(0xffffffffu, zc[c], 2);
            zc[c] += sB[c];
        }
        float mx = zc[0];
#pragma unroll
        for (int c = 1; c < 8; c++) mx = fmaxf(mx, zc[c]);
        float s = 0.f;
#pragma unroll
        for (int c = 0; c < 8; c++) s += __expf(zc[c] - mx);
        float lse = mx + __logf(s);
        float zsel = zc[0];
#pragma unroll
        for (int c = 1; c < 8; c++) if (xl[h] == c) zsel = zc[c];
        float total = lp[h] + 0.5f * (zsel - lse);
        if (m == 0) {
            int row = rowbase + q + 8 * h;
            out[row] = total;
        }
    }
}

extern "C" void kernel_launch(void* const* d_in, const int* in_sizes, int n_in,
                              void* d_out, int out_size) {
    (void)in_sizes; (void)n_in; (void)out_size;
    const int*   x    = (const int*)d_in[0];
    const float* Win0 = (const float*)d_in[1];
    const float* Win1 = (const float*)d_in[2];
    const float* Wh   = (const float*)d_in[3];
    const float* b    = (const float*)d_in[4];
    const float* Wlat = (const float*)d_in[5];
    const float* blat = (const float*)d_in[6];
    const float* Wcav = (const float*)d_in[7];
    const float* bcav = (const float*)d_in[8];
    float* out = (float*)d_out;
    rnn_fused<<<128, 256>>>(x, Win0, Win1, Wh, b, Wlat, blat, Wcav, bcav, out);
}

// round 5
// speedup vs baseline: 2.6529x; 1.6554x over previous
#include <cuda_runtime.h>
#include <cuda_fp16.h>
#include <stdint.h>

// RNN1DGeneral: B=16384, L=64, H=64, DEPTH=2, D_L=2, D_C=8, LPF=0.5
// fp16 mma.sync.m16n8k16; hidden state in registers across all 65 steps.
// R5 = R4 with the f16x2 min/max immediate-operand fix (register zero).

__device__ __forceinline__ void mma16816(float* c,
    uint32_t a0, uint32_t a1, uint32_t a2, uint32_t a3,
    uint32_t b0, uint32_t b1)
{
    asm("mma.sync.aligned.m16n8k16.row.col.f32.f16.f16.f32 "
        "{%0,%1,%2,%3},{%4,%5,%6,%7},{%8,%9},{%0,%1,%2,%3};"
        : "+f"(c[0]), "+f"(c[1]), "+f"(c[2]), "+f"(c[3])
        : "r"(a0), "r"(a1), "r"(a2), "r"(a3), "r"(b0), "r"(b1));
}

__device__ __forceinline__ uint32_t pack2(float lo, float hi) {
    __half2 h = __floats2half2_rn(lo, hi);
    return *reinterpret_cast<const uint32_t*>(&h);
}

// elementwise ELU on packed half2: max(v,0) + min(exp(v)-1, 0)
__device__ __forceinline__ uint32_t elu_h2(uint32_t u) {
    const uint32_t LOG2E2 = 0x3DC53DC5u;  // half2(1.4427, 1.4427)
    const uint32_t ONE2   = 0x3C003C00u;  // half2(1.0, 1.0)
    uint32_t zero = 0u;
    uint32_t t, e, em1, mx, mn, r;
    asm("mul.rn.f16x2 %0, %1, %2;" : "=r"(t) : "r"(u), "r"(LOG2E2));
    asm("ex2.approx.f16x2 %0, %1;" : "=r"(e) : "r"(t));
    asm("sub.rn.f16x2 %0, %1, %2;" : "=r"(em1) : "r"(e), "r"(ONE2));
    asm("max.f16x2 %0, %1, %2;" : "=r"(mx) : "r"(u), "r"(zero));
    asm("min.f16x2 %0, %1, %2;" : "=r"(mn) : "r"(em1), "r"(zero));
    asm("add.rn.f16x2 %0, %1, %2;" : "=r"(r) : "r"(mx), "r"(mn));
    return r;
}

__global__ void __launch_bounds__(256, 1) rnn_fused(
    const int*   __restrict__ x,     // [16384, 65]
    const float* __restrict__ Win0,  // [2, 64]
    const float* __restrict__ Win1,  // [64, 64]
    const float* __restrict__ Wh,    // [2, 64, 64]
    const float* __restrict__ bvec,  // [2, 64]
    const float* __restrict__ Wlat,  // [64, 2]
    const float* __restrict__ blat,  // [2]
    const float* __restrict__ Wcav,  // [128, 8]
    const float* __restrict__ bcav,  // [8]
    float*       __restrict__ out)   // [16384]
{
    // B-fragment pairs: sWp[((l*4+kt)*8+nt)*32 + lane] = {halves(k,k+1), halves(k+8,k+9)}
    // with k = 16*kt + 2*m, n = 8*nt + q, lane = 4*q+m. Conflict-free LDS.64.
    __shared__ uint2 sWp[3 * 4 * 8 * 32];      // l: 0=Wh0, 1=Win1, 2=Wh1  (24 KB)
    __shared__ float sV[3][72];                // V[b] = Win0[b]+b0 ; V[2] = b0
    __shared__ float sB1[64];                  // b1
    __shared__ float sWlat[64][2];
    __shared__ float sCav[128][8];
    __shared__ float sB[10];                   // [0..7]=bcav, [8..9]=blat

    const int tid = threadIdx.x;

    for (int i = tid; i < 3 * 4 * 8 * 32; i += 256) {
        int lane_ = i & 31, nt_ = (i >> 5) & 7, kt_ = (i >> 8) & 3, l_ = i >> 10;
        int q_ = lane_ >> 2, m_ = lane_ & 3;
        int n = 8 * nt_ + q_;
        int k0 = 16 * kt_ + 2 * m_;
        const float* src = (l_ == 0) ? Wh : (l_ == 1 ? Win1 : (Wh + 4096));
        uint2 u;
        u.x = pack2(src[k0 * 64 + n],       src[(k0 + 1) * 64 + n]);
        u.y = pack2(src[(k0 + 8) * 64 + n], src[(k0 + 9) * 64 + n]);
        sWp[i] = u;
    }
    for (int i = tid; i < 128 * 8; i += 256)
        (reinterpret_cast<float*>(sCav))[i] = Wcav[i];
    if (tid < 64) {
        int c = tid;
        float b0c = bvec[c];
        sV[0][c] = Win0[c] + b0c;
        sV[1][c] = Win0[64 + c] + b0c;
        sV[2][c] = b0c;
        sB1[c] = bvec[64 + c];
        sWlat[c][0] = Wlat[2 * c];
        sWlat[c][1] = Wlat[2 * c + 1];
    }
    if (tid < 8) sB[tid] = bcav[tid];
    if (tid < 2) sB[8 + tid] = blat[tid];
    __syncthreads();

    const int lane = tid & 31, warp = tid >> 5;
    const int q = lane >> 2, m = lane & 3;
    const int rowbase = blockIdx.x * 128 + warp * 16;

    const uint2* wp = sWp + lane;  // per-thread base; all offsets compile-time

    // pack per-row input bits; h in {0,1} -> row = rowbase + q + 8*h
    uint64_t xb[2];
    int xl[2];
#pragma unroll
    for (int rr = 0; rr < 2; rr++) {
        int r = rowbase + q + rr * 8;
        const int* xr = x + r * 65;
        uint64_t bits = 0;
#pragma unroll 8
        for (int t = 0; t < 64; t++)
            bits |= ((uint64_t)(xr[t] & 1)) << t;
        xb[rr] = bits;
        xl[rr] = xr[64] & 7;
    }

    // per-lane Wlat columns (this thread's cols: 8*nt + 2*m + j)
    float wl[8][2][2];
#pragma unroll
    for (int nt = 0; nt < 8; nt++)
#pragma unroll
        for (int j = 0; j < 2; j++) {
            int col = 8 * nt + 2 * m + j;
            wl[nt][j][0] = sWlat[col][0];
            wl[nt][j][1] = sWlat[col][1];
        }
    const float bl0 = sB[8], bl1 = sB[9];

    // hidden state A-fragments (post-ELU, fp16), zero init
    uint32_t h0f[4][4], h1f[4][4];
#pragma unroll
    for (int kt = 0; kt < 4; kt++)
#pragma unroll
        for (int i = 0; i < 4; i++) { h0f[kt][i] = 0u; h1f[kt][i] = 0u; }

    float lp[2] = {0.f, 0.f};
    float acc[8][4], acc2[8][4];

#pragma unroll 1
    for (int step = 0; step < 65; step++) {
        // ---- layer-0 acc init: Win0[one-hot(prev)] + b0 (per-row selected) ----
        int i0 = (step == 0) ? 2 : (int)((xb[0] >> (step - 1)) & 1ull);
        int i1 = (step == 0) ? 2 : (int)((xb[1] >> (step - 1)) & 1ull);
        const float* vr0 = sV[i0];
        const float* vr1 = sV[i1];
#pragma unroll
        for (int nt = 0; nt < 8; nt++) {
            float2 f0 = *reinterpret_cast<const float2*>(&vr0[8 * nt + 2 * m]);
            float2 f1 = *reinterpret_cast<const float2*>(&vr1[8 * nt + 2 * m]);
            acc[nt][0] = f0.x; acc[nt][1] = f0.y;
            acc[nt][2] = f1.x; acc[nt][3] = f1.y;
        }
        // ---- layer 0 GEMM: acc += h0 @ Wh0 ----
#pragma unroll
        for (int kt = 0; kt < 4; kt++)
#pragma unroll
            for (int nt = 0; nt < 8; nt++) {
                uint2 u = wp[((0 * 4 + kt) * 8 + nt) * 32];
                mma16816(acc[nt], h0f[kt][0], h0f[kt][1], h0f[kt][2], h0f[kt][3],
                         u.x, u.y);
            }
        // ---- layer-1 partial (independent of fresh h0): acc2 = b1 + h1 @ Wh1 ----
#pragma unroll
        for (int nt = 0; nt < 8; nt++) {
            float2 g = *reinterpret_cast<const float2*>(&sB1[8 * nt + 2 * m]);
            acc2[nt][0] = g.x; acc2[nt][1] = g.y;
            acc2[nt][2] = g.x; acc2[nt][3] = g.y;
        }
#pragma unroll
        for (int kt = 0; kt < 4; kt++)
#pragma unroll
            for (int nt = 0; nt < 8; nt++) {
                uint2 u = wp[((2 * 4 + kt) * 8 + nt) * 32];
                mma16816(acc2[nt], h1f[kt][0], h1f[kt][1], h1f[kt][2], h1f[kt][3],
                         u.x, u.y);
            }
        // ---- layer-0 activation: pack to fp16 then ELU in half2 ----
#pragma unroll
        for (int kt = 0; kt < 4; kt++) {
            h0f[kt][0] = elu_h2(pack2(acc[2 * kt][0], acc[2 * kt][1]));
            h0f[kt][1] = elu_h2(pack2(acc[2 * kt][2], acc[2 * kt][3]));
            h0f[kt][2] = elu_h2(pack2(acc[2 * kt + 1][0], acc[2 * kt + 1][1]));
            h0f[kt][3] = elu_h2(pack2(acc[2 * kt + 1][2], acc[2 * kt + 1][3]));
        }
        // ---- layer-1 rest: acc2 += h0_new @ Win1 ----
#pragma unroll
        for (int kt = 0; kt < 4; kt++)
#pragma unroll
            for (int nt = 0; nt < 8; nt++) {
                uint2 u = wp[((1 * 4 + kt) * 8 + nt) * 32];
                mma16816(acc2[nt], h0f[kt][0], h0f[kt][1], h0f[kt][2], h0f[kt][3],
                         u.x, u.y);
            }
#pragma unroll
        for (int kt = 0; kt < 4; kt++) {
            h1f[kt][0] = elu_h2(pack2(acc2[2 * kt][0], acc2[2 * kt][1]));
            h1f[kt][1] = elu_h2(pack2(acc2[2 * kt][2], acc2[2 * kt][3]));
            h1f[kt][2] = elu_h2(pack2(acc2[2 * kt + 1][0], acc2[2 * kt + 1][1]));
            h1f[kt][3] = elu_h2(pack2(acc2[2 * kt + 1][2], acc2[2 * kt + 1][3]));
        }

        // ---- per-step logits head (steps 0..63) from packed h1f ----
        if (step < 64) {
#pragma unroll
            for (int h = 0; h < 2; h++) {
                float z0 = 0.f, z1 = 0.f;
#pragma unroll
                for (int nt = 0; nt < 8; nt++) {
                    uint32_t u = h1f[nt >> 1][2 * (nt & 1) + h];
                    __half2 hh = *reinterpret_cast<const __half2*>(&u);
                    float c0 = __half2float(__low2half(hh));
                    float c1 = __half2float(__high2half(hh));
                    z0 += c0 * wl[nt][0][0] + c1 * wl[nt][1][0];
                    z1 += c0 * wl[nt][0][1] + c1 * wl[nt][1][1];
                }
                z0 += __shfl_xor_sync(0xffffffffu, z0, 1);
                z0 += __shfl_xor_sync(0xffffffffu, z0, 2);
                z1 += __shfl_xor_sync(0xffffffffu, z1, 1);
                z1 += __shfl_xor_sync(0xffffffffu, z1, 2);
                z0 += bl0; z1 += bl1;
                int bit = (int)((xb[h] >> step) & 1ull);
                float mx = fmaxf(z0, z1);
                float lse = mx + __logf(1.f + __expf(-fabsf(z0 - z1)));
                float zsel = bit ? z1 : z0;
                lp[h] += 0.5f * (zsel - lse);
            }
        }
    }

    // ---- cavity head: hF=[h0_final, h1_final] (128) @ Wcav + bcav ----
#pragma unroll
    for (int h = 0; h < 2; h++) {
        float zc[8];
#pragma unroll
        for (int c = 0; c < 8; c++) zc[c] = 0.f;
#pragma unroll
        for (int nt = 0; nt < 8; nt++) {
            int kt = nt >> 1;
            int ri = 2 * (nt & 1) + h;
            __half2 h2a = *reinterpret_cast<const __half2*>(&h0f[kt][ri]);
            __half2 h2b = *reinterpret_cast<const __half2*>(&h1f[kt][ri]);
            float v0 = __half2float(__low2half(h2a));
            float v1 = __half2float(__high2half(h2a));
            float a0v = __half2float(__low2half(h2b));
            float a1v = __half2float(__high2half(h2b));
            int col = 8 * nt + 2 * m;
#pragma unroll
            for (int c = 0; c < 8; c++) {
                zc[c] += v0 * sCav[col][c] + v1 * sCav[col + 1][c]
                       + a0v * sCav[64 + col][c] + a1v * sCav[64 + col + 1][c];
            }
        }
#pragma unroll
        for (int c = 0; c < 8; c++) {
            zc[c] += __shfl_xor_sync(0xffffffffu, zc[c], 1);
            zc[c] += __shfl_xor_sync(0xffffffffu, zc[c], 2);
            zc[c] += sB[c];
        }
        float mx = zc[0];
#pragma unroll
        for (int c = 1; c < 8; c++) mx = fmaxf(mx, zc[c]);
        float s = 0.f;
#pragma unroll
        for (int c = 0; c < 8; c++) s += __expf(zc[c] - mx);
        float lse = mx + __logf(s);
        float zsel = zc[0];
#pragma unroll
        for (int c = 1; c < 8; c++) if (xl[h] == c) zsel = zc[c];
        float total = lp[h] + 0.5f * (zsel - lse);
        if (m == 0) {
            int row = rowbase + q + 8 * h;
            out[row] = total;
        }
    }
}

extern "C" void kernel_launch(void* const* d_in, const int* in_sizes, int n_in,
                              void* d_out, int out_size) {
    (void)in_sizes; (void)n_in; (void)out_size;
    const int*   x    = (const int*)d_in[0];
    const float* Win0 = (const float*)d_in[1];
    const float* Win1 = (const float*)d_in[2];
    const float* Wh   = (const float*)d_in[3];
    const float* b    = (const float*)d_in[4];
    const float* Wlat = (const float*)d_in[5];
    const float* blat = (const float*)d_in[6];
    const float* Wcav = (const float*)d_in[7];
    const float* bcav = (const float*)d_in[8];
    float* out = (float*)d_out;
    rnn_fused<<<128, 256>>>(x, Win0, Win1, Wh, b, Wlat, blat, Wcav, bcav, out);
}